// round 15
// baseline (speedup 1.0000x reference)
#include <cuda_runtime.h>
#include <cuda_fp16.h>
#include <cstdint>

#define NP     100000
#define CCH    64
#define KK     27
#define EPSV   1e-5f
#define TILE_M 128
#define NBC    ((NP + TILE_M - 1) / TILE_M)   // 782

// ---------------- scratch (device globals; no allocation allowed) ----------------
__device__ float g_buf1[NP * CCH];
__device__ float g_buf2[NP * CCH];
__device__ __align__(16) __half g_h0[NP * CCH];          // half(feats)
__device__ __align__(16) __half g_h1[NP * CCH];          // half(relu(bn1(buf1)))
__device__ uint4 g_wf1[KK * 512];                        // W1 in mma-fragment order
__device__ uint4 g_wf2[KK * 512];                        // W2 in mma-fragment order
__device__ float g_part1[NBC * 2 * CCH];
__device__ float g_part2[NBC * 2 * CCH];
__device__ float g_stats1[2 * CCH];   // [0:64) scale, [64:128) shift
__device__ float g_stats2[2 * CCH];

// ---------------- PTX helpers ----------------
__device__ __forceinline__ void ldsm4(uint32_t& r0, uint32_t& r1, uint32_t& r2, uint32_t& r3,
                                      uint32_t addr) {
    asm volatile("ldmatrix.sync.aligned.m8n8.x4.shared.b16 {%0,%1,%2,%3}, [%4];"
                 : "=r"(r0), "=r"(r1), "=r"(r2), "=r"(r3) : "r"(addr));
}
__device__ __forceinline__ void mma16816(float* d, uint32_t a0, uint32_t a1, uint32_t a2,
                                         uint32_t a3, uint32_t b0, uint32_t b1) {
    asm volatile(
        "mma.sync.aligned.m16n8k16.row.col.f32.f16.f16.f32 "
        "{%0,%1,%2,%3}, {%4,%5,%6,%7}, {%8,%9}, {%0,%1,%2,%3};"
        : "+f"(d[0]), "+f"(d[1]), "+f"(d[2]), "+f"(d[3])
        : "r"(a0), "r"(a1), "r"(a2), "r"(a3), "r"(b0), "r"(b1));
}
#define CP_ASYNC_Z(dst, src, sz) \
    asm volatile("cp.async.cg.shared.global [%0], [%1], 16, %2;" \
                 :: "r"(dst), "l"(src), "r"(sz) : "memory")
#define CP_COMMIT()  asm volatile("cp.async.commit_group;" ::: "memory")
#define CP_WAIT0()   asm volatile("cp.async.wait_group 0;" ::: "memory")

// SMEM map (byte offsets from 128-aligned base):
//   A buffers: 2 stages x (128 rows x 128B, SW128)  @ 0       (32768 B)
//   RED/RED2:  256 + 256 fp32                        @ 32768 / 33792
#define SM_AB(s)   ((uint32_t)(((s) & 1) * 16384))
#define SM_RED     32768
#define SM_RED2    33792
#define SMEM_BYTES (34816 + 128)

// ---------------------------------------------------------------------------
// Sparse conv: dst[n,d] = sum_k sum_c src_h[idx[k,n]][c] * mask[k,n] * W[k][c][d]
// fp16 operands, fp32 accum; FULL N=64 per CTA (no work duplication);
// slim register budget for 5 CTAs/SM (20 warps):
//   - per-warp 2-stage cp.async A-ring (wait_group 0, issue-after-wait)
//   - idx/mask register-prefetched 1 iter ahead, shfl-distributed
//   - B fragment-order LDG.128, 1-ahead rotation; ldsm single-bank
// ---------------------------------------------------------------------------
__global__ __launch_bounds__(128, 5)
void conv_h(const __half* __restrict__ src,
            const int*    __restrict__ idx,
            const float*  __restrict__ mask,
            const uint4*  __restrict__ Wf,
            float*        __restrict__ dst,
            float*        __restrict__ part)
{
    extern __shared__ char smraw[];
    char* smc = (char*)(((uintptr_t)smraw + 127) & ~(uintptr_t)127);
    uint32_t sb;
    asm("{ .reg .u64 t; cvta.to.shared.u64 t, %1; cvt.u32.u64 %0, t; }" : "=r"(sb) : "l"(smc));
    float* RED  = (float*)(smc + SM_RED);
    float* RED2 = (float*)(smc + SM_RED2);

    const int tid  = threadIdx.x;
    const int w    = tid >> 5;
    const int lane = tid & 31;
    const int n0   = blockIdx.x * TILE_M;
    const int n    = n0 + tid;            // row this lane OWNS (idx/mask prefetch)
    const int gq   = lane >> 2;
    const int tq   = lane & 3;
    const int mrow = lane & 7;
    const int mi   = lane >> 3;
    const int chk  = lane & 7;            // 16B chunk this lane copies
    const int rsub = lane >> 3;           // row-subgroup (0..3)

    // base LDSM address for ks=0 (per-ks delta applied inline: xor pattern)
    const uint32_t a_row0 = (uint32_t)(w * 32 + (mi & 1) * 8 + mrow) * 128u;
    const uint32_t a_col0 = (uint32_t)(mi >> 1);   // 0/1 within 16B pairs

    // ---- prologue: issue A(0); prefetch idx/mask for A(1) ----
    {
        int   gi_own = 0; float mm_own = 0.f;
        if (n < NP) { gi_own = idx[n]; mm_own = mask[n]; }
#pragma unroll
        for (int j = 0; j < 8; ++j) {
            const int rl = 4 * j + rsub;
            int   gi = __shfl_sync(0xFFFFFFFFu, gi_own, rl);
            float mm = __shfl_sync(0xFFFFFFFFu, mm_own, rl);
            const char* gp = (const char*)(src + (size_t)gi * CCH) + chk * 16;
            uint32_t sdst = sb + SM_AB(0) + (uint32_t)(w * 32 + rl) * 128u
                          + (uint32_t)((chk ^ (rl & 7)) * 16);
            CP_ASYNC_Z(sdst, gp, (mm != 0.f) ? 16u : 0u);
        }
        CP_COMMIT();
    }
    int   idx_c = 0;
    float m_c   = 0.f;
    if (n < NP) { idx_c = idx[(size_t)1 * NP + n]; m_c = mask[(size_t)1 * NP + n]; }

    float acc[2][8][4];
#pragma unroll
    for (int t = 0; t < 2; ++t)
#pragma unroll
        for (int nb = 0; nb < 8; ++nb)
#pragma unroll
            for (int i = 0; i < 4; ++i) acc[t][nb][i] = 0.f;

    for (int k = 0; k < KK; ++k) {
        CP_WAIT0();            // per-warp: A(k) resident
        __syncwarp();          // order async writes vs this warp's ldsm

        // ---- issue A(k+1) into the other buffer (read finished last iter) ----
        if (k + 1 < KK) {
#pragma unroll
            for (int j = 0; j < 8; ++j) {
                const int rl = 4 * j + rsub;
                int   gi = __shfl_sync(0xFFFFFFFFu, idx_c, rl);
                float mm = __shfl_sync(0xFFFFFFFFu, m_c, rl);
                const char* gp = (const char*)(src + (size_t)gi * CCH) + chk * 16;
                uint32_t sdst = sb + SM_AB(k + 1) + (uint32_t)(w * 32 + rl) * 128u
                              + (uint32_t)((chk ^ (rl & 7)) * 16);
                CP_ASYNC_Z(sdst, gp, (mm != 0.f) ? 16u : 0u);
            }
            CP_COMMIT();
        }
        // prefetch idx/mask for stage k+2 (lands during this iter's MMA)
        idx_c = 0; m_c = 0.f;
        if (k + 2 < KK && n < NP) {
            idx_c = idx[(size_t)(k + 2) * NP + n];
            m_c   = mask[(size_t)(k + 2) * NP + n];
        }

        // ---- MMA: A single-bank ldsm; B fragment-order LDG 1-ahead ----
        const uint32_t ab = sb + SM_AB(k);
        const uint4* wfk = Wf + (size_t)k * 512 + lane;
        uint4 ba = wfk[0];
        uint32_t afr[8];
#pragma unroll
        for (int ks = 0; ks < 4; ++ks) {
            const uint32_t aoff = ab + a_row0 + (uint32_t)(((2 * ks + a_col0) ^ mrow) * 16);
            ldsm4(afr[0], afr[1], afr[2], afr[3], aoff);
            ldsm4(afr[4], afr[5], afr[6], afr[7], aoff + 2048u);
#pragma unroll
            for (int nbp = 0; nbp < 4; ++nbp) {
                const int i = ks * 4 + nbp;
                uint4 bc = ba;
                if (i + 1 < 16) ba = wfk[(size_t)(i + 1) * 32];
                mma16816(acc[0][2 * nbp],     afr[0], afr[1], afr[2], afr[3], bc.x, bc.y);
                mma16816(acc[0][2 * nbp + 1], afr[0], afr[1], afr[2], afr[3], bc.z, bc.w);
                mma16816(acc[1][2 * nbp],     afr[4], afr[5], afr[6], afr[7], bc.x, bc.y);
                mma16816(acc[1][2 * nbp + 1], afr[4], afr[5], afr[6], afr[7], bc.z, bc.w);
            }
        }
    }

    // ---- epilogue: direct dst stores + shuffle-reduced BN partials ----
#pragma unroll
    for (int t = 0; t < 2; ++t) {
#pragma unroll
        for (int nb = 0; nb < 8; ++nb) {
            int rlo = n0 + w * 32 + t * 16 + gq;
            if (rlo < NP)
                *(float2*)(dst + (size_t)rlo * CCH + nb * 8 + 2 * tq) =
                    make_float2(acc[t][nb][0], acc[t][nb][1]);
            if (rlo + 8 < NP)
                *(float2*)(dst + (size_t)(rlo + 8) * CCH + nb * 8 + 2 * tq) =
                    make_float2(acc[t][nb][2], acc[t][nb][3]);
        }
    }
    // per-channel sums over this warp's 32 rows; rows >= NP hold exact zeros
#pragma unroll
    for (int cidx = 0; cidx < 16; ++cidx) {
        const int nb = cidx >> 1, j = cidx & 1;
        float p = acc[0][nb][j] + acc[0][nb][2 + j] + acc[1][nb][j] + acc[1][nb][2 + j];
        float q = acc[0][nb][j] * acc[0][nb][j];
        q = fmaf(acc[0][nb][2 + j], acc[0][nb][2 + j], q);
        q = fmaf(acc[1][nb][j],     acc[1][nb][j],     q);
        q = fmaf(acc[1][nb][2 + j], acc[1][nb][2 + j], q);
#pragma unroll
        for (int d = 4; d < 32; d <<= 1) {      // reduce over gq (lanes stride 4)
            p += __shfl_xor_sync(0xFFFFFFFFu, p, d);
            q += __shfl_xor_sync(0xFFFFFFFFu, q, d);
        }
        if (lane < 4) {                          // gq == 0
            RED[w * 64 + nb * 8 + 2 * tq + j]  = p;
            RED2[w * 64 + nb * 8 + 2 * tq + j] = q;
        }
    }
    __syncthreads();
    if (tid < CCH) {
        float s = 0.f, s2 = 0.f;
#pragma unroll
        for (int ww = 0; ww < 4; ++ww) { s += RED[ww * 64 + tid]; s2 += RED2[ww * 64 + tid]; }
        part[blockIdx.x * (2 * CCH) + tid]       = s;
        part[blockIdx.x * (2 * CCH) + CCH + tid] = s2;
    }
}

// ---------------------------------------------------------------------------
// prep: pack W[k][c][d] into mma-fragment order (lane = gq*4+tq, frag = ks*4+nbp)
// ---------------------------------------------------------------------------
__global__ __launch_bounds__(512)
void prep_wf(const float* __restrict__ W, uint4* __restrict__ Wf)
{
    const int k    = blockIdx.x;
    const int tid  = threadIdx.x;       // 512 = 16 frags x 32 lanes
    const int lane = tid & 31;
    const int f    = tid >> 5;
    const int ks   = f >> 2, nbp = f & 3;
    const int gq   = lane >> 2, tq = lane & 3;
    const int c0   = 16 * ks + 2 * tq;
    const int d0   = 16 * nbp + gq;
    const float* Wk = W + (size_t)k * CCH * CCH;
    union { __half2 h[4]; uint4 u; } o;
    o.h[0] = __floats2half2_rn(Wk[(c0 + 0) * CCH + d0],     Wk[(c0 + 1) * CCH + d0]);
    o.h[1] = __floats2half2_rn(Wk[(c0 + 8) * CCH + d0],     Wk[(c0 + 9) * CCH + d0]);
    o.h[2] = __floats2half2_rn(Wk[(c0 + 0) * CCH + d0 + 8], Wk[(c0 + 1) * CCH + d0 + 8]);
    o.h[3] = __floats2half2_rn(Wk[(c0 + 8) * CCH + d0 + 8], Wk[(c0 + 9) * CCH + d0 + 8]);
    Wf[(size_t)k * 512 + f * 32 + lane] = o.u;
}

// ---------------------------------------------------------------------------
// feats -> half  (8 elements / thread)
// ---------------------------------------------------------------------------
__global__ __launch_bounds__(256)
void f2h_kernel(const float* __restrict__ in, __half* __restrict__ out)
{
    int i = blockIdx.x * 256 + threadIdx.x;
    if (i < NP * CCH / 8) {
        const float4* p = (const float4*)in + 2 * i;
        float4 v0 = p[0], v1 = p[1];
        union { __half2 hh[4]; uint4 u; } cv;
        cv.hh[0] = __floats2half2_rn(v0.x, v0.y);
        cv.hh[1] = __floats2half2_rn(v0.z, v0.w);
        cv.hh[2] = __floats2half2_rn(v1.x, v1.y);
        cv.hh[3] = __floats2half2_rn(v1.z, v1.w);
        ((uint4*)out)[i] = cv.u;
    }
}

// ---------------------------------------------------------------------------
// h1 = half(relu(buf1*scale1 + shift1))   (8 elements / thread)
// ---------------------------------------------------------------------------
__global__ __launch_bounds__(256)
void bnrelu2h_kernel(const float* __restrict__ in, const float* __restrict__ stats,
                     __half* __restrict__ out)
{
    __shared__ float scsh[128];
    if (threadIdx.x < 128) scsh[threadIdx.x] = stats[threadIdx.x];
    __syncthreads();
    int i = blockIdx.x * 256 + threadIdx.x;
    if (i < NP * CCH / 8) {
        const float4* p = (const float4*)in + 2 * i;
        float4 v0 = p[0], v1 = p[1];
        int c0 = (i * 8) & 63;
        const float* sc = scsh, * sh = scsh + 64;
        float t[8];
        t[0] = fmaxf(fmaf(v0.x, sc[c0 + 0], sh[c0 + 0]), 0.f);
        t[1] = fmaxf(fmaf(v0.y, sc[c0 + 1], sh[c0 + 1]), 0.f);
        t[2] = fmaxf(fmaf(v0.z, sc[c0 + 2], sh[c0 + 2]), 0.f);
        t[3] = fmaxf(fmaf(v0.w, sc[c0 + 3], sh[c0 + 3]), 0.f);
        t[4] = fmaxf(fmaf(v1.x, sc[c0 + 4], sh[c0 + 4]), 0.f);
        t[5] = fmaxf(fmaf(v1.y, sc[c0 + 5], sh[c0 + 5]), 0.f);
        t[6] = fmaxf(fmaf(v1.z, sc[c0 + 6], sh[c0 + 6]), 0.f);
        t[7] = fmaxf(fmaf(v1.w, sc[c0 + 7], sh[c0 + 7]), 0.f);
        union { __half2 hh[4]; uint4 u; } cv;
        cv.hh[0] = __floats2half2_rn(t[0], t[1]);
        cv.hh[1] = __floats2half2_rn(t[2], t[3]);
        cv.hh[2] = __floats2half2_rn(t[4], t[5]);
        cv.hh[3] = __floats2half2_rn(t[6], t[7]);
        ((uint4*)out)[i] = cv.u;
    }
}

// ---------------------------------------------------------------------------
// Per-channel stats finalize: scale = gamma*rsqrt(var+eps), shift = beta - mean*scale
// ---------------------------------------------------------------------------
__global__ __launch_bounds__(256)
void finalize_kernel(const float* __restrict__ part,
                     const float* __restrict__ gamma,
                     const float* __restrict__ beta,
                     float*       __restrict__ stats)
{
    const int c   = blockIdx.x;
    const int tid = threadIdx.x;
    float s = 0.f, s2 = 0.f;
    for (int b = tid; b < NBC; b += 256) {
        s  += part[b * (2 * CCH) + c];
        s2 += part[b * (2 * CCH) + CCH + c];
    }
    __shared__ float r1[256], r2[256];
    r1[tid] = s; r2[tid] = s2;
    __syncthreads();
    for (int o = 128; o > 0; o >>= 1) {
        if (tid < o) { r1[tid] += r1[tid + o]; r2[tid] += r2[tid + o]; }
        __syncthreads();
    }
    if (tid == 0) {
        float mean = r1[0] * (1.0f / NP);
        float var  = r2[0] * (1.0f / NP) - mean * mean;
        float istd = rsqrtf(var + EPSV);
        float sc   = istd * gamma[c];
        stats[c]       = sc;
        stats[CCH + c] = beta[c] - mean * sc;
    }
}

// ---------------------------------------------------------------------------
// out = relu( buf2*scale2 + shift2 + feats )
// ---------------------------------------------------------------------------
__global__ __launch_bounds__(256)
void epi_kernel(const float* __restrict__ buf2,
                const float* __restrict__ stats,
                const float* __restrict__ feats,
                float*       __restrict__ out)
{
    __shared__ float sc[CCH], sh[CCH];
    if (threadIdx.x < CCH) {
        sc[threadIdx.x] = stats[threadIdx.x];
        sh[threadIdx.x] = stats[CCH + threadIdx.x];
    }
    __syncthreads();
    int i = blockIdx.x * blockDim.x + threadIdx.x;   // float4 index
    if (i < NP * CCH / 4) {
        float4 v = ((const float4*)buf2)[i];
        float4 f = ((const float4*)feats)[i];
        int c = (i * 4) & 63;
        v.x = fmaxf(fmaf(v.x, sc[c + 0], sh[c + 0]) + f.x, 0.f);
        v.y = fmaxf(fmaf(v.y, sc[c + 1], sh[c + 1]) + f.y, 0.f);
        v.z = fmaxf(fmaf(v.z, sc[c + 2], sh[c + 2]) + f.z, 0.f);
        v.w = fmaxf(fmaf(v.w, sc[c + 3], sh[c + 3]) + f.w, 0.f);
        ((float4*)out)[i] = v;
    }
}

// ---------------------------------------------------------------------------
extern "C" void kernel_launch(void* const* d_in, const int* in_sizes, int n_in,
                              void* d_out, int out_size)
{
    const float* feats  = (const float*)d_in[0];
    const float* W1     = (const float*)d_in[1];
    const float* gamma1 = (const float*)d_in[2];
    const float* beta1  = (const float*)d_in[3];
    const float* W2     = (const float*)d_in[4];
    const float* gamma2 = (const float*)d_in[5];
    const float* beta2  = (const float*)d_in[6];
    const int*   idx1   = (const int*)  d_in[7];
    const float* mask1  = (const float*)d_in[8];
    const int*   idx2   = (const int*)  d_in[9];
    const float* mask2  = (const float*)d_in[10];
    float* out = (float*)d_out;

    float *buf1, *buf2, *part1, *part2, *st1, *st2;
    __half *h0, *h1;
    uint4 *wf1, *wf2;
    cudaGetSymbolAddress((void**)&buf1,  g_buf1);
    cudaGetSymbolAddress((void**)&buf2,  g_buf2);
    cudaGetSymbolAddress((void**)&h0,    g_h0);
    cudaGetSymbolAddress((void**)&h1,    g_h1);
    cudaGetSymbolAddress((void**)&wf1,   g_wf1);
    cudaGetSymbolAddress((void**)&wf2,   g_wf2);
    cudaGetSymbolAddress((void**)&part1, g_part1);
    cudaGetSymbolAddress((void**)&part2, g_part2);
    cudaGetSymbolAddress((void**)&st1,   g_stats1);
    cudaGetSymbolAddress((void**)&st2,   g_stats2);

    cudaFuncSetAttribute(conv_h, cudaFuncAttributeMaxDynamicSharedMemorySize, SMEM_BYTES);

    const int cvt_blocks = (NP * CCH / 8 + 255) / 256;
    prep_wf<<<KK, 512>>>(W1, wf1);
    prep_wf<<<KK, 512>>>(W2, wf2);
    f2h_kernel<<<cvt_blocks, 256>>>(feats, h0);

    conv_h<<<NBC, 128, SMEM_BYTES>>>(h0, idx1, mask1, wf1, buf1, part1);
    finalize_kernel<<<CCH, 256>>>(part1, gamma1, beta1, st1);
    bnrelu2h_kernel<<<cvt_blocks, 256>>>(buf1, st1, h1);
    conv_h<<<NBC, 128, SMEM_BYTES>>>(h1, idx2, mask2, wf2, buf2, part2);
    finalize_kernel<<<CCH, 256>>>(part2, gamma2, beta2, st2);

    const int epi_blocks = (NP * CCH / 4 + 255) / 256;
    epi_kernel<<<epi_blocks, 256>>>(buf2, st2, feats, out);
}

// round 16
// speedup vs baseline: 1.7079x; 1.7079x over previous
#include <cuda_runtime.h>
#include <cuda_fp16.h>
#include <cstdint>

#define NP     100000
#define CCH    64
#define KK     27
#define EPSV   1e-5f
#define TILE_M 128
#define NBC    ((NP + TILE_M - 1) / TILE_M)   // 782

// ---------------- scratch (device globals; no allocation allowed) ----------------
__device__ float g_buf1[NP * CCH];
__device__ float g_buf2[NP * CCH];
__device__ __align__(16) __half g_h0[NP * CCH];          // half(feats)
__device__ __align__(16) __half g_h1[NP * CCH];          // half(relu(bn1(buf1)))
__device__ uint4 g_wf1[KK * 512];                        // W1 in mma-fragment order
__device__ uint4 g_wf2[KK * 512];                        // W2 in mma-fragment order
__device__ float g_part1[2 * CCH * NBC];                 // TRANSPOSED: [c][tile]
__device__ float g_part2[2 * CCH * NBC];
__device__ float g_stats1[2 * CCH];   // [0:64) scale, [64:128) shift
__device__ float g_stats2[2 * CCH];

// ---------------- PTX helpers ----------------
__device__ __forceinline__ void ldsm4(uint32_t& r0, uint32_t& r1, uint32_t& r2, uint32_t& r3,
                                      uint32_t addr) {
    asm volatile("ldmatrix.sync.aligned.m8n8.x4.shared.b16 {%0,%1,%2,%3}, [%4];"
                 : "=r"(r0), "=r"(r1), "=r"(r2), "=r"(r3) : "r"(addr));
}
__device__ __forceinline__ void mma16816(float* d, uint32_t a0, uint32_t a1, uint32_t a2,
                                         uint32_t a3, uint32_t b0, uint32_t b1) {
    asm volatile(
        "mma.sync.aligned.m16n8k16.row.col.f32.f16.f16.f32 "
        "{%0,%1,%2,%3}, {%4,%5,%6,%7}, {%8,%9}, {%0,%1,%2,%3};"
        : "+f"(d[0]), "+f"(d[1]), "+f"(d[2]), "+f"(d[3])
        : "r"(a0), "r"(a1), "r"(a2), "r"(a3), "r"(b0), "r"(b1));
}
#define CP_ASYNC_Z(dst, src, sz) \
    asm volatile("cp.async.cg.shared.global [%0], [%1], 16, %2;" \
                 :: "r"(dst), "l"(src), "r"(sz) : "memory")
#define CP_COMMIT()  asm volatile("cp.async.commit_group;" ::: "memory")
#define CP_WAIT1()   asm volatile("cp.async.wait_group 1;" ::: "memory")

// SMEM map (byte offsets from 128-aligned base):
//   A buffers: 3 stages x (128 rows x 128B, SW128)  @ 0       (49152 B)
//   RED/RED2:  256 + 256 fp32                       @ 49152 / 50176
#define SM_AB(s)   ((uint32_t)(((s) % 3) * 16384))
#define SM_RED     49152
#define SM_RED2    50176
#define SMEM_BYTES (51200 + 128)

// ---------------------------------------------------------------------------
// Sparse conv (R13 configuration — measured local optimum):
//   dst[n,d] = sum_k sum_c src_h[idx[k,n]][c] * mask[k,n] * W[k][c][d]
//   - per-warp 3-stage cp.async A-ring (wait_group 1), no CTA barrier in loop
//   - idx/mask register-prefetched 1 iter ahead, shfl-distributed at issue
//   - B fragment-order LDG.128 (L1 broadcast) 2-ahead; ldsm pipelined 1 ks ahead
//   - BN partials written TRANSPOSED [c][tile] (coalesced finalize reads)
// ---------------------------------------------------------------------------
__global__ __launch_bounds__(128, 4)
void conv_h(const __half* __restrict__ src,
            const int*    __restrict__ idx,
            const float*  __restrict__ mask,
            const uint4*  __restrict__ Wf,
            float*        __restrict__ dst,
            float*        __restrict__ part)
{
    extern __shared__ char smraw[];
    char* smc = (char*)(((uintptr_t)smraw + 127) & ~(uintptr_t)127);
    uint32_t sb;
    asm("{ .reg .u64 t; cvta.to.shared.u64 t, %1; cvt.u32.u64 %0, t; }" : "=r"(sb) : "l"(smc));
    float* RED  = (float*)(smc + SM_RED);
    float* RED2 = (float*)(smc + SM_RED2);

    const int tid  = threadIdx.x;
    const int w    = tid >> 5;
    const int lane = tid & 31;
    const int n0   = blockIdx.x * TILE_M;
    const int n    = n0 + tid;            // row this lane OWNS (idx/mask prefetch)
    const int gq   = lane >> 2;
    const int tq   = lane & 3;
    const int mrow = lane & 7;
    const int mi   = lane >> 3;
    const int chk  = lane & 7;            // 16B chunk this lane copies
    const int rsub = lane >> 3;           // row-subgroup (0..3)

    // loop-invariant A LDSM addresses (relative; add stage base at use)
    uint32_t a_rel[4];
#pragma unroll
    for (int ks = 0; ks < 4; ++ks)
        a_rel[ks] = (uint32_t)(w * 32 + (mi & 1) * 8 + mrow) * 128u
                  + (uint32_t)((2 * ks + (mi >> 1)) ^ mrow) * 16u;

    // ---- prologue: issue A(0), A(1); prefetch idx/mask for A(2) ----
#pragma unroll
    for (int s = 0; s < 2; ++s) {
        int   gi_own = 0; float mm_own = 0.f;
        if (n < NP) { gi_own = idx[(size_t)s * NP + n]; mm_own = mask[(size_t)s * NP + n]; }
#pragma unroll
        for (int j = 0; j < 8; ++j) {
            const int rl = 4 * j + rsub;
            int   gi = __shfl_sync(0xFFFFFFFFu, gi_own, rl);
            float mm = __shfl_sync(0xFFFFFFFFu, mm_own, rl);
            const char* gp = (const char*)(src + (size_t)gi * CCH) + chk * 16;
            uint32_t sdst = sb + SM_AB(s) + (uint32_t)(w * 32 + rl) * 128u
                          + (uint32_t)((chk ^ (rl & 7)) * 16);
            CP_ASYNC_Z(sdst, gp, (mm != 0.f) ? 16u : 0u);
        }
        CP_COMMIT();
    }
    int   idx_c = 0;
    float m_c   = 0.f;
    if (n < NP) { idx_c = idx[(size_t)2 * NP + n]; m_c = mask[(size_t)2 * NP + n]; }

    float acc[2][8][4];
#pragma unroll
    for (int t = 0; t < 2; ++t)
#pragma unroll
        for (int nb = 0; nb < 8; ++nb)
#pragma unroll
            for (int i = 0; i < 4; ++i) acc[t][nb][i] = 0.f;

    for (int k = 0; k < KK; ++k) {
        CP_WAIT1();            // per-warp: A(k) resident (only A(k+1) may pend)
        __syncwarp();          // order async writes vs this warp's ldsm

        // ---- issue A(k+2) from prefetched registers, divergence-free ----
        if (k + 2 < KK) {
#pragma unroll
            for (int j = 0; j < 8; ++j) {
                const int rl = 4 * j + rsub;
                int   gi = __shfl_sync(0xFFFFFFFFu, idx_c, rl);
                float mm = __shfl_sync(0xFFFFFFFFu, m_c, rl);
                const char* gp = (const char*)(src + (size_t)gi * CCH) + chk * 16;
                uint32_t sdst = sb + SM_AB(k + 2) + (uint32_t)(w * 32 + rl) * 128u
                              + (uint32_t)((chk ^ (rl & 7)) * 16);
                CP_ASYNC_Z(sdst, gp, (mm != 0.f) ? 16u : 0u);
            }
        }
        CP_COMMIT();
        // prefetch idx/mask for stage k+3 (lands during this iter's MMA)
        idx_c = 0; m_c = 0.f;
        if (k + 3 < KK && n < NP) {
            idx_c = idx[(size_t)(k + 3) * NP + n];
            m_c   = mask[(size_t)(k + 3) * NP + n];
        }

        // ---- MMA: A ldsm pipelined one ks ahead; B fragment-order LDG 2-ahead ----
        const uint32_t ab = sb + SM_AB(k);
        const uint4* wfk = Wf + (size_t)k * 512 + lane;
        uint4 ba = wfk[0];
        uint4 bb = wfk[32];
        uint32_t afr[2][8];
        ldsm4(afr[0][0], afr[0][1], afr[0][2], afr[0][3], ab + a_rel[0]);
        ldsm4(afr[0][4], afr[0][5], afr[0][6], afr[0][7], ab + a_rel[0] + 2048u);
#pragma unroll
        for (int ks = 0; ks < 4; ++ks) {
            const int cur = ks & 1, nxt = cur ^ 1;
            if (ks < 3) {
                ldsm4(afr[nxt][0], afr[nxt][1], afr[nxt][2], afr[nxt][3], ab + a_rel[ks + 1]);
                ldsm4(afr[nxt][4], afr[nxt][5], afr[nxt][6], afr[nxt][7], ab + a_rel[ks + 1] + 2048u);
            }
#pragma unroll
            for (int nbp = 0; nbp < 4; ++nbp) {
                const int i = ks * 4 + nbp;
                uint4 bc = ba;
                ba = bb;
                if (i + 2 < 16) bb = wfk[(size_t)(i + 2) * 32];
                mma16816(acc[0][2 * nbp],     afr[cur][0], afr[cur][1], afr[cur][2], afr[cur][3], bc.x, bc.y);
                mma16816(acc[0][2 * nbp + 1], afr[cur][0], afr[cur][1], afr[cur][2], afr[cur][3], bc.z, bc.w);
                mma16816(acc[1][2 * nbp],     afr[cur][4], afr[cur][5], afr[cur][6], afr[cur][7], bc.x, bc.y);
                mma16816(acc[1][2 * nbp + 1], afr[cur][4], afr[cur][5], afr[cur][6], afr[cur][7], bc.z, bc.w);
            }
        }
    }

    // ---- epilogue: direct dst stores + shuffle-reduced BN partials ----
#pragma unroll
    for (int t = 0; t < 2; ++t) {
#pragma unroll
        for (int nb = 0; nb < 8; ++nb) {
            int rlo = n0 + w * 32 + t * 16 + gq;
            if (rlo < NP)
                *(float2*)(dst + (size_t)rlo * CCH + nb * 8 + 2 * tq) =
                    make_float2(acc[t][nb][0], acc[t][nb][1]);
            if (rlo + 8 < NP)
                *(float2*)(dst + (size_t)(rlo + 8) * CCH + nb * 8 + 2 * tq) =
                    make_float2(acc[t][nb][2], acc[t][nb][3]);
        }
    }
    // per-channel sums over this warp's 32 rows; rows >= NP hold exact zeros
#pragma unroll
    for (int cidx = 0; cidx < 16; ++cidx) {
        const int nb = cidx >> 1, j = cidx & 1;
        float p = acc[0][nb][j] + acc[0][nb][2 + j] + acc[1][nb][j] + acc[1][nb][2 + j];
        float q = acc[0][nb][j] * acc[0][nb][j];
        q = fmaf(acc[0][nb][2 + j], acc[0][nb][2 + j], q);
        q = fmaf(acc[1][nb][j],     acc[1][nb][j],     q);
        q = fmaf(acc[1][nb][2 + j], acc[1][nb][2 + j], q);
#pragma unroll
        for (int d = 4; d < 32; d <<= 1) {      // reduce over gq (lanes stride 4)
            p += __shfl_xor_sync(0xFFFFFFFFu, p, d);
            q += __shfl_xor_sync(0xFFFFFFFFu, q, d);
        }
        if (lane < 4) {                          // gq == 0
            RED[w * 64 + nb * 8 + 2 * tq + j]  = p;
            RED2[w * 64 + nb * 8 + 2 * tq + j] = q;
        }
    }
    __syncthreads();
    if (tid < CCH) {
        float s = 0.f, s2 = 0.f;
#pragma unroll
        for (int ww = 0; ww < 4; ++ww) { s += RED[ww * 64 + tid]; s2 += RED2[ww * 64 + tid]; }
        // TRANSPOSED layout: coalesced reads in finalize; scattered fire-and-forget writes here
        part[(size_t)tid * NBC + blockIdx.x]         = s;
        part[(size_t)(CCH + tid) * NBC + blockIdx.x] = s2;
    }
}

// ---------------------------------------------------------------------------
// prep: pack W[k][c][d] into mma-fragment order; grid = 2*KK (W1 then W2)
// ---------------------------------------------------------------------------
__global__ __launch_bounds__(512)
void prep_wf2(const float* __restrict__ W1, uint4* __restrict__ Wf1,
              const float* __restrict__ W2, uint4* __restrict__ Wf2)
{
    const int b    = blockIdx.x;
    const int k    = (b < KK) ? b : (b - KK);
    const float* W = (b < KK) ? W1 : W2;
    uint4* Wf      = (b < KK) ? Wf1 : Wf2;
    const int tid  = threadIdx.x;       // 512 = 16 frags x 32 lanes
    const int lane = tid & 31;
    const int f    = tid >> 5;
    const int ks   = f >> 2, nbp = f & 3;
    const int gq   = lane >> 2, tq = lane & 3;
    const int c0   = 16 * ks + 2 * tq;
    const int d0   = 16 * nbp + gq;
    const float* Wk = W + (size_t)k * CCH * CCH;
    union { __half2 h[4]; uint4 u; } o;
    o.h[0] = __floats2half2_rn(Wk[(c0 + 0) * CCH + d0],     Wk[(c0 + 1) * CCH + d0]);
    o.h[1] = __floats2half2_rn(Wk[(c0 + 8) * CCH + d0],     Wk[(c0 + 9) * CCH + d0]);
    o.h[2] = __floats2half2_rn(Wk[(c0 + 0) * CCH + d0 + 8], Wk[(c0 + 1) * CCH + d0 + 8]);
    o.h[3] = __floats2half2_rn(Wk[(c0 + 8) * CCH + d0 + 8], Wk[(c0 + 9) * CCH + d0 + 8]);
    Wf[(size_t)k * 512 + f * 32 + lane] = o.u;
}

// ---------------------------------------------------------------------------
// feats -> half  (8 elements / thread)
// ---------------------------------------------------------------------------
__global__ __launch_bounds__(256)
void f2h_kernel(const float* __restrict__ in, __half* __restrict__ out)
{
    int i = blockIdx.x * 256 + threadIdx.x;
    if (i < NP * CCH / 8) {
        const float4* p = (const float4*)in + 2 * i;
        float4 v0 = p[0], v1 = p[1];
        union { __half2 hh[4]; uint4 u; } cv;
        cv.hh[0] = __floats2half2_rn(v0.x, v0.y);
        cv.hh[1] = __floats2half2_rn(v0.z, v0.w);
        cv.hh[2] = __floats2half2_rn(v1.x, v1.y);
        cv.hh[3] = __floats2half2_rn(v1.z, v1.w);
        ((uint4*)out)[i] = cv.u;
    }
}

// ---------------------------------------------------------------------------
// h1 = half(relu(buf1*scale1 + shift1))   (8 elements / thread)
// ---------------------------------------------------------------------------
__global__ __launch_bounds__(256)
void bnrelu2h_kernel(const float* __restrict__ in, const float* __restrict__ stats,
                     __half* __restrict__ out)
{
    __shared__ float scsh[128];
    if (threadIdx.x < 128) scsh[threadIdx.x] = stats[threadIdx.x];
    __syncthreads();
    int i = blockIdx.x * 256 + threadIdx.x;
    if (i < NP * CCH / 8) {
        const float4* p = (const float4*)in + 2 * i;
        float4 v0 = p[0], v1 = p[1];
        int c0 = (i * 8) & 63;
        const float* sc = scsh, * sh = scsh + 64;
        float t[8];
        t[0] = fmaxf(fmaf(v0.x, sc[c0 + 0], sh[c0 + 0]), 0.f);
        t[1] = fmaxf(fmaf(v0.y, sc[c0 + 1], sh[c0 + 1]), 0.f);
        t[2] = fmaxf(fmaf(v0.z, sc[c0 + 2], sh[c0 + 2]), 0.f);
        t[3] = fmaxf(fmaf(v0.w, sc[c0 + 3], sh[c0 + 3]), 0.f);
        t[4] = fmaxf(fmaf(v1.x, sc[c0 + 4], sh[c0 + 4]), 0.f);
        t[5] = fmaxf(fmaf(v1.y, sc[c0 + 5], sh[c0 + 5]), 0.f);
        t[6] = fmaxf(fmaf(v1.z, sc[c0 + 6], sh[c0 + 6]), 0.f);
        t[7] = fmaxf(fmaf(v1.w, sc[c0 + 7], sh[c0 + 7]), 0.f);
        union { __half2 hh[4]; uint4 u; } cv;
        cv.hh[0] = __floats2half2_rn(t[0], t[1]);
        cv.hh[1] = __floats2half2_rn(t[2], t[3]);
        cv.hh[2] = __floats2half2_rn(t[4], t[5]);
        cv.hh[3] = __floats2half2_rn(t[6], t[7]);
        ((uint4*)out)[i] = cv.u;
    }
}

// ---------------------------------------------------------------------------
// Per-channel stats finalize (coalesced reads of transposed partials)
// ---------------------------------------------------------------------------
__global__ __launch_bounds__(256)
void finalize_kernel(const float* __restrict__ part,
                     const float* __restrict__ gamma,
                     const float* __restrict__ beta,
                     float*       __restrict__ stats)
{
    const int c   = blockIdx.x;
    const int tid = threadIdx.x;
    const float* p1 = part + (size_t)c * NBC;
    const float* p2 = part + (size_t)(CCH + c) * NBC;
    float s = 0.f, s2 = 0.f;
    for (int b = tid; b < NBC; b += 256) {   // contiguous, coalesced
        s  += p1[b];
        s2 += p2[b];
    }
    __shared__ float r1[256], r2[256];
    r1[tid] = s; r2[tid] = s2;
    __syncthreads();
    for (int o = 128; o > 0; o >>= 1) {
        if (tid < o) { r1[tid] += r1[tid + o]; r2[tid] += r2[tid + o]; }
        __syncthreads();
    }
    if (tid == 0) {
        float mean = r1[0] * (1.0f / NP);
        float var  = r2[0] * (1.0f / NP) - mean * mean;
        float istd = rsqrtf(var + EPSV);
        float sc   = istd * gamma[c];
        stats[c]       = sc;
        stats[CCH + c] = beta[c] - mean * sc;
    }
}

// ---------------------------------------------------------------------------
// out = relu( buf2*scale2 + shift2 + feats )
// ---------------------------------------------------------------------------
__global__ __launch_bounds__(256)
void epi_kernel(const float* __restrict__ buf2,
                const float* __restrict__ stats,
                const float* __restrict__ feats,
                float*       __restrict__ out)
{
    __shared__ float sc[CCH], sh[CCH];
    if (threadIdx.x < CCH) {
        sc[threadIdx.x] = stats[threadIdx.x];
        sh[threadIdx.x] = stats[CCH + threadIdx.x];
    }
    __syncthreads();
    int i = blockIdx.x * blockDim.x + threadIdx.x;   // float4 index
    if (i < NP * CCH / 4) {
        float4 v = ((const float4*)buf2)[i];
        float4 f = ((const float4*)feats)[i];
        int c = (i * 4) & 63;
        v.x = fmaxf(fmaf(v.x, sc[c + 0], sh[c + 0]) + f.x, 0.f);
        v.y = fmaxf(fmaf(v.y, sc[c + 1], sh[c + 1]) + f.y, 0.f);
        v.z = fmaxf(fmaf(v.z, sc[c + 2], sh[c + 2]) + f.z, 0.f);
        v.w = fmaxf(fmaf(v.w, sc[c + 3], sh[c + 3]) + f.w, 0.f);
        ((float4*)out)[i] = v;
    }
}

// ---------------------------------------------------------------------------
extern "C" void kernel_launch(void* const* d_in, const int* in_sizes, int n_in,
                              void* d_out, int out_size)
{
    const float* feats  = (const float*)d_in[0];
    const float* W1     = (const float*)d_in[1];
    const float* gamma1 = (const float*)d_in[2];
    const float* beta1  = (const float*)d_in[3];
    const float* W2     = (const float*)d_in[4];
    const float* gamma2 = (const float*)d_in[5];
    const float* beta2  = (const float*)d_in[6];
    const int*   idx1   = (const int*)  d_in[7];
    const float* mask1  = (const float*)d_in[8];
    const int*   idx2   = (const int*)  d_in[9];
    const float* mask2  = (const float*)d_in[10];
    float* out = (float*)d_out;

    float *buf1, *buf2, *part1, *part2, *st1, *st2;
    __half *h0, *h1;
    uint4 *wf1, *wf2;
    cudaGetSymbolAddress((void**)&buf1,  g_buf1);
    cudaGetSymbolAddress((void**)&buf2,  g_buf2);
    cudaGetSymbolAddress((void**)&h0,    g_h0);
    cudaGetSymbolAddress((void**)&h1,    g_h1);
    cudaGetSymbolAddress((void**)&wf1,   g_wf1);
    cudaGetSymbolAddress((void**)&wf2,   g_wf2);
    cudaGetSymbolAddress((void**)&part1, g_part1);
    cudaGetSymbolAddress((void**)&part2, g_part2);
    cudaGetSymbolAddress((void**)&st1,   g_stats1);
    cudaGetSymbolAddress((void**)&st2,   g_stats2);

    cudaFuncSetAttribute(conv_h, cudaFuncAttributeMaxDynamicSharedMemorySize, SMEM_BYTES);

    const int cvt_blocks = (NP * CCH / 8 + 255) / 256;
    prep_wf2<<<2 * KK, 512>>>(W1, wf1, W2, wf2);
    f2h_kernel<<<cvt_blocks, 256>>>(feats, h0);

    conv_h<<<NBC, 128, SMEM_BYTES>>>(h0, idx1, mask1, wf1, buf1, part1);
    finalize_kernel<<<CCH, 256>>>(part1, gamma1, beta1, st1);
    bnrelu2h_kernel<<<cvt_blocks, 256>>>(buf1, st1, h1);
    conv_h<<<NBC, 128, SMEM_BYTES>>>(h1, idx2, mask2, wf2, buf2, part2);
    finalize_kernel<<<CCH, 256>>>(part2, gamma2, beta2, st2);

    const int epi_blocks = (NP * CCH / 4 + 255) / 256;
    epi_kernel<<<epi_blocks, 256>>>(buf2, st2, feats, out);
}